// round 3
// baseline (speedup 1.0000x reference)
#include <cuda_runtime.h>
#include <cstdint>
#include <cstddef>

#define DEV_INLINE __device__ __forceinline__
typedef unsigned long long u64;

constexpr int D        = 512;       // feature dim
constexpr int FV       = 12;        // video frames
constexpr int NP       = 6;         // frame pairs
constexpr int PSTRIDE  = D + 2;     // u64 stride per pair-row (16B pad)
constexpr int THREADS  = 128;       // 4 warps
constexpr int RPW      = 10;        // text rows per warp, single pass
constexpr int ROWS_CTA = 4 * RPW;   // 40 rows per CTA

// scratch (allocation-free: __device__ globals)
__device__ float g_part_min[4096];
__device__ float g_part_max[4096];
__device__ float g_rowval[1024];
__device__ float g_diagval[1024];

DEV_INLINE u64 ffma2(u64 a, u64 b, u64 c) {
    u64 d;
    asm("fma.rn.f32x2 %0, %1, %2, %3;" : "=l"(d) : "l"(a), "l"(b), "l"(c));
    return d;
}
DEV_INLINE u64 pk2(float lo, float hi) {
    u64 r;
    asm("mov.b64 %0, {%1, %2};" : "=l"(r) : "f"(lo), "f"(hi));
    return r;
}
DEV_INLINE u64 dup2(float x) {
    u64 r;
    asm("mov.b64 %0, {%1, %1};" : "=l"(r) : "f"(x));
    return r;
}
DEV_INLINE void unpk2(u64 v, float& lo, float& hi) {
    asm("mov.b64 {%0, %1}, %2;" : "=f"(lo), "=f"(hi) : "l"(v));
}

// ---------------------------------------------------------------------------
// Kernel 1: per-(sample, chunk) min/max cosine over (40 text rows) x (12 video).
// Video stored in shared as FRAME-PAIR packed u64: sp[p][d] = (v[2p][d], v[2p+1][d]).
// Warp layout: 2 f-groups x 16 d-lanes; fg owns 3 pair-rows (6 frames).
// Each f32x2 accumulator covers 2 frames -> RPW=10 rows per warp per pass,
// halving video LDS bytes per text row vs the unpacked scheme.
// ---------------------------------------------------------------------------
__global__ void __launch_bounds__(THREADS, 4)
sample_minmax_kernel(const float* __restrict__ text,
                     const float* __restrict__ video,
                     int T, int chunks)
{
    __shared__ __align__(16) u64 sp[NP * PSTRIDE];
    __shared__ float s_vinv[FV];
    __shared__ float s_wmin[4], s_wmax[4];

    const int b     = blockIdx.x / chunks;
    const int chunk = blockIdx.x % chunks;
    const int tid   = threadIdx.x;
    const int warp  = tid >> 5;
    const int lane  = tid & 31;
    const int fg    = lane >> 4;    // 0..1 : frame-pair group (frames 6*fg .. 6*fg+5)
    const int dl    = lane & 15;    // 0..15: D-slice lane

    const float4* vsrc = reinterpret_cast<const float4*>(video + (size_t)b * FV * D);

    // ---- stage video as packed frame pairs ----
    #pragma unroll
    for (int i = tid; i < NP * 128; i += THREADS) {
        int p = i >> 7;            // pair index
        int c = i & 127;           // float4 column
        float4 a = vsrc[(2 * p    ) * 128 + c];
        float4 e = vsrc[(2 * p + 1) * 128 + c];
        u64* dst = &sp[p * PSTRIDE + 4 * c];
        *reinterpret_cast<ulonglong2*>(dst)     = make_ulonglong2(pk2(a.x, e.x), pk2(a.y, e.y));
        *reinterpret_cast<ulonglong2*>(dst + 2) = make_ulonglong2(pk2(a.z, e.z), pk2(a.w, e.w));
    }

    // ---- inverse norms of the 12 video rows (3 per warp, from global/L2) ----
    #pragma unroll
    for (int k = 0; k < 3; k++) {
        int f = warp * 3 + k;
        float s = 0.f;
        #pragma unroll
        for (int c = lane; c < 128; c += 32) {
            float4 x = vsrc[f * 128 + c];
            s += x.x * x.x + x.y * x.y + x.z * x.z + x.w * x.w;
        }
        #pragma unroll
        for (int o = 16; o > 0; o >>= 1) s += __shfl_xor_sync(0xffffffffu, s, o);
        if (lane == 0) s_vinv[f] = rsqrtf(s);
    }
    __syncthreads();

    float vinv[6];
    #pragma unroll
    for (int j = 0; j < 6; j++) vinv[j] = s_vinv[6 * fg + j];

    const u64* vp0 = &sp[(fg * 3 + 0) * PSTRIDE];
    const u64* vp1 = &sp[(fg * 3 + 1) * PSTRIDE];
    const u64* vp2 = &sp[(fg * 3 + 2) * PSTRIDE];

    // ---- this warp's 10 text rows (clamped duplicates are harmless) ----
    const float* tb = text + (size_t)b * (size_t)T * D;
    const int base  = chunk * ROWS_CTA + warp * RPW;
    const u64* trp[RPW];
    #pragma unroll
    for (int r = 0; r < RPW; r++) {
        int tt = base + r; if (tt > T - 1) tt = T - 1;
        trp[r] = reinterpret_cast<const u64*>(tb + (size_t)tt * D);
    }

    u64 acc[RPW][3];        // [row][pair] : (dot frame 2p, dot frame 2p+1) partials
    u64 nrm[RPW];           // (sum t_even^2, sum t_odd^2) partials
    #pragma unroll
    for (int r = 0; r < RPW; r++) {
        acc[r][0] = 0ull; acc[r][1] = 0ull; acc[r][2] = 0ull; nrm[r] = 0ull;
    }

    #pragma unroll
    for (int s = 0; s < 16; s++) {
        const int eo = dl + 16 * s;                // u64 (=2-float) index into text row
        const int e2 = eo * 2;                     // element index into pair rows
        ulonglong2 q0 = *reinterpret_cast<const ulonglong2*>(vp0 + e2);
        ulonglong2 q1 = *reinterpret_cast<const ulonglong2*>(vp1 + e2);
        ulonglong2 q2 = *reinterpret_cast<const ulonglong2*>(vp2 + e2);
        #pragma unroll
        for (int r = 0; r < RPW; r++) {
            u64 tv = trp[r][eo];                   // (t[2eo], t[2eo+1])
            float t0, t1; unpk2(tv, t0, t1);
            u64 td0 = dup2(t0);
            u64 td1 = dup2(t1);
            acc[r][0] = ffma2(td0, q0.x, acc[r][0]);
            acc[r][0] = ffma2(td1, q0.y, acc[r][0]);
            acc[r][1] = ffma2(td0, q1.x, acc[r][1]);
            acc[r][1] = ffma2(td1, q1.y, acc[r][1]);
            acc[r][2] = ffma2(td0, q2.x, acc[r][2]);
            acc[r][2] = ffma2(td1, q2.y, acc[r][2]);
            nrm[r]    = ffma2(tv, tv, nrm[r]);
        }
    }

    // ---- reduction tail: once per warp, 10 independent row chains ----
    float wcmin = 1e30f, wcmax = -1e30f;
    #pragma unroll
    for (int r = 0; r < RPW; r++) {
        float c0, c1, c2, c3, c4, c5, n0, n1;
        unpk2(acc[r][0], c0, c1);
        unpk2(acc[r][1], c2, c3);
        unpk2(acc[r][2], c4, c5);
        unpk2(nrm[r], n0, n1);
        float ns = n0 + n1;
        #pragma unroll
        for (int o = 1; o <= 8; o <<= 1) {         // reduce across the 16 d-lanes
            c0 += __shfl_xor_sync(0xffffffffu, c0, o);
            c1 += __shfl_xor_sync(0xffffffffu, c1, o);
            c2 += __shfl_xor_sync(0xffffffffu, c2, o);
            c3 += __shfl_xor_sync(0xffffffffu, c3, o);
            c4 += __shfl_xor_sync(0xffffffffu, c4, o);
            c5 += __shfl_xor_sync(0xffffffffu, c5, o);
            ns += __shfl_xor_sync(0xffffffffu, ns, o);
        }
        float rin = rsqrtf(ns);
        c0 *= rin * vinv[0];
        c1 *= rin * vinv[1];
        c2 *= rin * vinv[2];
        c3 *= rin * vinv[3];
        c4 *= rin * vinv[4];
        c5 *= rin * vinv[5];
        float cmn = fminf(fminf(fminf(c0, c1), fminf(c2, c3)), fminf(c4, c5));
        float cmx = fmaxf(fmaxf(fmaxf(c0, c1), fmaxf(c2, c3)), fmaxf(c4, c5));
        cmn = fminf(cmn, __shfl_xor_sync(0xffffffffu, cmn, 16));   // combine fgs
        cmx = fmaxf(cmx, __shfl_xor_sync(0xffffffffu, cmx, 16));
        wcmin = fminf(wcmin, cmn);
        wcmax = fmaxf(wcmax, cmx);
    }

    if (lane == 0) { s_wmin[warp] = wcmin; s_wmax[warp] = wcmax; }
    __syncthreads();
    if (tid == 0) {
        float mn = fminf(fminf(s_wmin[0], s_wmin[1]), fminf(s_wmin[2], s_wmin[3]));
        float mx = fmaxf(fmaxf(s_wmax[0], s_wmax[1]), fmaxf(s_wmax[2], s_wmax[3]));
        g_part_min[blockIdx.x] = mn;   // min cos (chunk partial)
        g_part_max[blockIdx.x] = mx;   // max cos (chunk partial)
    }
}

// ---------------------------------------------------------------------------
// Kernel 2: combine chunk partials, global min/max, per-sample row/diag values.
// ---------------------------------------------------------------------------
__global__ void finalize_kernel(int B, int chunks)
{
    __shared__ float smx[256], smn[256];
    __shared__ float sh_mn, sh_inv;
    __shared__ float s_cmin[1024], s_cmax[1024];
    const int tid = threadIdx.x;

    float cmx = -1e30f, cmn = 1e30f;
    for (int i = tid; i < B; i += 256) {
        float m0 = 1e30f, m1 = -1e30f;
        for (int c = 0; c < chunks; c++) {
            m0 = fminf(m0, g_part_min[i * chunks + c]);
            m1 = fmaxf(m1, g_part_max[i * chunks + c]);
        }
        s_cmin[i] = m0;   // min cos for sample i  -> dmax_i = 1 - m0
        s_cmax[i] = m1;   // max cos for sample i  -> dmin_i = 1 - m1
        cmn = fminf(cmn, m0);
        cmx = fmaxf(cmx, m1);
    }
    smx[tid] = cmx; smn[tid] = cmn;
    __syncthreads();
    #pragma unroll
    for (int o = 128; o > 0; o >>= 1) {
        if (tid < o) {
            smx[tid] = fmaxf(smx[tid], smx[tid + o]);
            smn[tid] = fminf(smn[tid], smn[tid + o]);
        }
        __syncthreads();
    }
    if (tid == 0) {
        float mn = 1.0f - smx[0];        // min over all dis entries
        float mx = 1.0f - smn[0];        // max over all dis entries
        sh_mn  = mn;
        sh_inv = 1.0f / (mx - mn);
    }
    __syncthreads();
    const float mn  = sh_mn;
    const float inv = sh_inv;
    for (int i = tid; i < B; i += 256) {
        g_rowval[i]  = ((1.0f - s_cmin[i]) - mn) * inv;   // off-diagonal of row i
        g_diagval[i] = ((1.0f - s_cmax[i]) - mn) * inv;   // diagonal value
    }
}

// ---------------------------------------------------------------------------
// Kernel 3: fill the BxB output. One block per row, float4 stores.
// ---------------------------------------------------------------------------
__global__ void fill_kernel(float* __restrict__ out, int B)
{
    const int i  = blockIdx.x;
    const float rv = g_rowval[i];
    const float dv = g_diagval[i];
    float4* orow = reinterpret_cast<float4*>(out + (size_t)i * B);
    const int n4 = B >> 2;
    for (int c = threadIdx.x; c < n4; c += blockDim.x) {
        float4 v = make_float4(rv, rv, rv, rv);
        if (c == (i >> 2)) reinterpret_cast<float*>(&v)[i & 3] = dv;
        orow[c] = v;
    }
}

// ---------------------------------------------------------------------------
extern "C" void kernel_launch(void* const* d_in, const int* in_sizes, int n_in,
                              void* d_out, int out_size)
{
    const float* text  = (const float*)d_in[0];   // [B, T, D] fp32
    const float* video = (const float*)d_in[1];   // [B, F, D] fp32
    float* out = (float*)d_out;                   // [B, B] fp32

    const int B = in_sizes[1] / (FV * D);
    const int T = in_sizes[0] / (B * D);
    const int chunks = (T + ROWS_CTA - 1) / ROWS_CTA;   // 2 for T=77

    sample_minmax_kernel<<<B * chunks, THREADS>>>(text, video, T, chunks);
    finalize_kernel<<<1, 256>>>(B, chunks);
    fill_kernel<<<B, 128>>>(out, B);
}